// round 1
// baseline (speedup 1.0000x reference)
#include <cuda_runtime.h>
#include <math.h>
#include <stdint.h>

// Problem constants (fixed by the dataset)
#define DB 256
#define DS 128
#define DH 768
#define DA 512
#define DN 10
#define DC 3
#define DK 3
#define MTOK (DB*DS)          // 32768 tokens

// -------- scratch (no allocations allowed; __device__ globals) --------
__device__ float g_vote[(size_t)DK*MTOK*DC];     // flat (K,M,C) ~1.2 MB
__device__ float g_h2[(size_t)MTOK*DH];          // ~100 MB
__device__ float g_a1[(size_t)MTOK*DA];          // ~64 MB

__device__ __forceinline__ float gelu_exact(float v) {
    return 0.5f*v*(1.0f + erff(v*0.70710678118654752f));
}
__device__ __forceinline__ float sigmoidf_(float z) {
    return 1.0f/(1.0f + expf(-z));
}

// ============================================================================
// Kernel 1: per-token semantic capsules + dynamic routing -> g_vote (K,M,C flat)
// Block = 256 threads (8 warps) x 2 tokens/warp = 16 tokens/block.
// sem_w (10*768*3 floats = 90KB) staged in dynamic smem; lane-stride-3 access
// pattern is bank-conflict-free (3 coprime with 32).
// ============================================================================
__global__ __launch_bounds__(256) void capsule_kernel(
    const float* __restrict__ x, const int* __restrict__ tptr,
    const float* __restrict__ sem_w, const float* __restrict__ sem_b,
    const float* __restrict__ route_w, float* __restrict__ vote_out)
{
    extern __shared__ float s_semw[];           // [N*H*C] = 23040 floats
    for (int i = threadIdx.x; i < DN*DH*DC; i += 256) s_semw[i] = sem_w[i];
    __syncthreads();

    const int t = *tptr;
    const int warp = threadIdx.x >> 5;
    const int lane = threadIdx.x & 31;

    for (int tt = 0; tt < 2; tt++) {
        const int m = blockIdx.x*16 + warp*2 + tt;
        const float* xr = x + (size_t)m*DH;

        float acc[30];
        #pragma unroll
        for (int q = 0; q < 30; q++) acc[q] = 0.f;

        #pragma unroll 4
        for (int hb = 0; hb < DH/32; hb++) {
            const int h = hb*32 + lane;
            const float xv = xr[h];
            const float* wp = s_semw + h*3;     // + n*2304 + c per q
            #pragma unroll
            for (int q = 0; q < 30; q++) {
                acc[q] += xv * wp[(q/3)*(DH*DC) + (q%3)];
            }
        }
        // butterfly reduce each of the 30 partial sums across the warp
        #pragma unroll
        for (int q = 0; q < 30; q++) {
            #pragma unroll
            for (int off = 16; off > 0; off >>= 1)
                acc[q] += __shfl_xor_sync(0xffffffffu, acc[q], off);
        }

        if (lane == 0) {
            // semv[q], q = n*3 + c
            float semv[30];
            #pragma unroll
            for (int q = 0; q < 30; q++) semv[q] = acc[q] + sem_b[q];

            // squash over tasks, per c
            float fc[3];
            #pragma unroll
            for (int c = 0; c < 3; c++) {
                float sn = 1e-16f;
                #pragma unroll
                for (int n = 0; n < 10; n++) { float v = semv[n*3+c]; sn += v*v; }
                fc[c] = sn/(1.f+sn)*rsqrtf(sn);
            }
            // row-major rescramble: p = c*N + n = n2*C + c2
            float u[10][3];
            #pragma unroll
            for (int p = 0; p < 30; p++) {
                const int c = p/10, n = p%10;
                u[p/3][p%3] = semv[n*3+c]*fc[c];
            }
            // priors[k][n][d] = sum_c u[n][c]*route_w[k][n][c][d]
            float pri[3][10][3];
            #pragma unroll
            for (int k = 0; k < 3; k++)
                #pragma unroll
                for (int n = 0; n < 10; n++)
                    #pragma unroll
                    for (int d = 0; d < 3; d++) {
                        float s = 0.f;
                        #pragma unroll
                        for (int c = 0; c < 3; c++)
                            s += u[n][c]*route_w[((k*10+n)*3+c)*3+d];
                        pri[k][n][d] = s;
                    }
            // dynamic routing (3 iters). Masked tasks get -10000 logits.
            float logits[3][10];
            #pragma unroll
            for (int k = 0; k < 3; k++)
                #pragma unroll
                for (int n = 0; n < 10; n++) logits[k][n] = 0.f;
            float vote[3][3];
            #pragma unroll
            for (int it = 0; it < 3; it++) {
                #pragma unroll
                for (int k = 0; k < 3; k++) {
                    float l[10], mx = -1e30f;
                    #pragma unroll
                    for (int n = 0; n < 10; n++) {
                        l[n] = (n <= t) ? logits[k][n] : -10000.f;
                        mx = fmaxf(mx, l[n]);
                    }
                    float e[10], se = 0.f;
                    #pragma unroll
                    for (int n = 0; n < 10; n++) { e[n] = expf(l[n]-mx); se += e[n]; }
                    const float inv = 1.f/se;
                    #pragma unroll
                    for (int d = 0; d < 3; d++) {
                        float v = 0.f;
                        #pragma unroll
                        for (int n = 0; n < 10; n++) v += e[n]*pri[k][n][d];
                        vote[k][d] = v*inv;
                    }
                    if (it < 2) {
                        float sn = 1e-16f;
                        #pragma unroll
                        for (int d = 0; d < 3; d++) sn += vote[k][d]*vote[k][d];
                        const float fo = sn/(1.f+sn)*rsqrtf(sn);
                        #pragma unroll
                        for (int n = 0; n < 10; n++) {
                            float dv = 0.f;
                            #pragma unroll
                            for (int d = 0; d < 3; d++) dv += pri[k][n][d]*vote[k][d];
                            logits[k][n] += dv*fo;
                        }
                    }
                }
            }
            #pragma unroll
            for (int k = 0; k < 3; k++)
                #pragma unroll
                for (int d = 0; d < 3; d++)
                    vote_out[((size_t)k*MTOK + m)*3 + d] = vote[k][d];
        }
    }
}

// ============================================================================
// Kernel 2: h2 = x + (v9 @ larger_w + larger_b) * sigmoid(s*elarger[t])
// Flat vote read: token m uses g_vote[9m .. 9m+8] (the row-major reshape trick).
// Block handles 32 tokens; larger_w (27KB) + bias/gate in static smem.
// ============================================================================
__global__ __launch_bounds__(256) void larger_kernel(
    const float* __restrict__ x, const int* __restrict__ tptr,
    const int* __restrict__ sptr,
    const float* __restrict__ lw, const float* __restrict__ lb,
    const float* __restrict__ elarger, const float* __restrict__ voteflat,
    float* __restrict__ h2)
{
    __shared__ float s_lw[9*DH];
    __shared__ float s_lb[DH];
    __shared__ float s_g[DH];
    __shared__ float s_v[32*9];

    const int t = *tptr;
    const float sf = (float)(*sptr);

    for (int i = threadIdx.x; i < 9*DH; i += 256) s_lw[i] = lw[i];
    for (int i = threadIdx.x; i < DH; i += 256) {
        s_lb[i] = lb[i];
        s_g[i]  = sigmoidf_(sf*elarger[t*DH + i]);
    }
    const int m0 = blockIdx.x*32;
    for (int i = threadIdx.x; i < 32*9; i += 256)
        s_v[i] = voteflat[(size_t)m0*9 + i];
    __syncthreads();

    for (int tt = 0; tt < 32; tt++) {
        const int m = m0 + tt;
        float v[9];
        #pragma unroll
        for (int j = 0; j < 9; j++) v[j] = s_v[tt*9 + j];
        #pragma unroll
        for (int r = 0; r < 3; r++) {
            const int e = threadIdx.x + r*256;
            float a = s_lb[e];
            #pragma unroll
            for (int j = 0; j < 9; j++) a += v[j]*s_lw[j*DH + e];
            h2[(size_t)m*DH + e] = x[(size_t)m*DH + e] + a*s_g[e];
        }
    }
}

// ============================================================================
// Kernels 3/4: fp32 SGEMM 128x128x8, 8x8 micro-tiles, fused GELU+gate epilogue.
// MODE 0: C = gelu(A@B + bias)*gate           (fc1 -> a1)
// MODE 1: C = xres + gelu(A@B + bias)*gate    (fc2 -> out)
// M fixed = 32768 (divisible by 128); N,K divisible by 128/8.
// ============================================================================
template<int MODE>
__global__ __launch_bounds__(256) void gemm_kernel(
    const float* __restrict__ A, const float* __restrict__ Bw,
    const float* __restrict__ bias, const float* __restrict__ egate,
    const int* __restrict__ tptr, const int* __restrict__ sptr,
    const float* __restrict__ xres, float* __restrict__ C,
    int N, int K)
{
    constexpr int BM = 128, BN = 128, BK = 8, TM = 8, TN = 8;
    __shared__ float As[BK][BM];
    __shared__ float Bs[BK][BN];

    const int tid = threadIdx.x;
    const int rowBase = blockIdx.y*BM;
    const int colBase = blockIdx.x*BN;

    const int aRow = tid >> 1;          // 0..127
    const int aCol = (tid & 1)*4;       // 0 or 4
    const int bRow = tid >> 5;          // 0..7
    const int bCol = (tid & 31)*4;      // 0..124

    const float* Ab = A + (size_t)rowBase*K;

    float acc[TM][TN];
    #pragma unroll
    for (int i = 0; i < TM; i++)
        #pragma unroll
        for (int j = 0; j < TN; j++) acc[i][j] = 0.f;

    const int tr = (tid >> 4)*TM;
    const int tc = (tid & 15)*TN;

    for (int k0 = 0; k0 < K; k0 += BK) {
        const float4 av = *(const float4*)(Ab + (size_t)aRow*K + k0 + aCol);
        As[aCol+0][aRow] = av.x;
        As[aCol+1][aRow] = av.y;
        As[aCol+2][aRow] = av.z;
        As[aCol+3][aRow] = av.w;
        const float4 bv = *(const float4*)(Bw + (size_t)(k0+bRow)*N + colBase + bCol);
        *(float4*)(&Bs[bRow][bCol]) = bv;
        __syncthreads();

        #pragma unroll
        for (int kk = 0; kk < BK; kk++) {
            float ra[TM], rb[TN];
            #pragma unroll
            for (int i = 0; i < TM; i += 4)
                *(float4*)(&ra[i]) = *(const float4*)(&As[kk][tr+i]);
            #pragma unroll
            for (int j = 0; j < TN; j += 4)
                *(float4*)(&rb[j]) = *(const float4*)(&Bs[kk][tc+j]);
            #pragma unroll
            for (int i = 0; i < TM; i++)
                #pragma unroll
                for (int j = 0; j < TN; j++)
                    acc[i][j] += ra[i]*rb[j];
        }
        __syncthreads();
    }

    const int t = *tptr;
    const float sf = (float)(*sptr);
    float gate[TN], bb[TN];
    #pragma unroll
    for (int j = 0; j < TN; j++) {
        const int n = colBase + tc + j;
        bb[j]   = bias[n];
        gate[j] = sigmoidf_(sf*egate[t*N + n]);
    }
    #pragma unroll
    for (int i = 0; i < TM; i++) {
        const size_t m = rowBase + tr + i;
        #pragma unroll
        for (int j = 0; j < TN; j++) {
            const int n = colBase + tc + j;
            float v = gelu_exact(acc[i][j] + bb[j])*gate[j];
            if (MODE == 1) v += xres[m*N + n];
            C[m*N + n] = v;
        }
    }
}

// ============================================================================
extern "C" void kernel_launch(void* const* d_in, const int* in_sizes, int n_in,
                              void* d_out, int out_size)
{
    const float* x       = (const float*)d_in[0];
    const int*   tptr    = (const int*)  d_in[1];
    const int*   sptr    = (const int*)  d_in[2];
    const float* fc1_w   = (const float*)d_in[3];
    const float* fc1_b   = (const float*)d_in[4];
    const float* fc2_w   = (const float*)d_in[5];
    const float* fc2_b   = (const float*)d_in[6];
    const float* efc1    = (const float*)d_in[7];
    const float* efc2    = (const float*)d_in[8];
    const float* sem_w   = (const float*)d_in[9];
    const float* sem_b   = (const float*)d_in[10];
    const float* route_w = (const float*)d_in[11];
    const float* lw      = (const float*)d_in[12];
    const float* lb      = (const float*)d_in[13];
    const float* elarger = (const float*)d_in[14];
    float* out = (float*)d_out;

    float *vote, *h2, *a1;
    cudaGetSymbolAddress((void**)&vote, g_vote);
    cudaGetSymbolAddress((void**)&h2,   g_h2);
    cudaGetSymbolAddress((void**)&a1,   g_a1);

    // capsule kernel needs 90KB dynamic smem (> 48KB default)
    const int capsule_smem = DN*DH*DC*(int)sizeof(float);   // 92160
    cudaFuncSetAttribute(capsule_kernel,
                         cudaFuncAttributeMaxDynamicSharedMemorySize, capsule_smem);

    capsule_kernel<<<MTOK/16, 256, capsule_smem>>>(x, tptr, sem_w, sem_b, route_w, vote);
    larger_kernel<<<MTOK/32, 256>>>(x, tptr, sptr, lw, lb, elarger, vote, h2);
    gemm_kernel<0><<<dim3(DA/128, MTOK/128), 256>>>(h2, fc1_w, fc1_b, efc1,
                                                    tptr, sptr, nullptr, a1, DA, DH);
    gemm_kernel<1><<<dim3(DH/128, MTOK/128), 256>>>(a1, fc2_w, fc2_b, efc2,
                                                    tptr, sptr, x, out, DH, DA);
}

// round 4
// speedup vs baseline: 2.3190x; 2.3190x over previous
#include <cuda_runtime.h>
#include <math.h>
#include <stdint.h>

// Problem constants (fixed by the dataset)
#define DB 256
#define DS 128
#define DH 768
#define DA 512
#define DN 10
#define DC 3
#define DK 3
#define MTOK (DB*DS)          // 32768 tokens

// -------- scratch (no allocations allowed; __device__ globals) --------
__device__ float g_vote[(size_t)DK*MTOK*DC];     // flat (K,M,C) ~1.2 MB
__device__ float g_h2[(size_t)MTOK*DH];          // ~100 MB
__device__ float g_a1[(size_t)MTOK*DA];          // ~64 MB

__device__ __forceinline__ float gelu_exact(float v) {
    return 0.5f*v*(1.0f + erff(v*0.70710678118654752f));
}
__device__ __forceinline__ float sigmoidf_(float z) {
    return 1.0f/(1.0f + expf(-z));
}

// ============================================================================
// Kernel 1: per-token semantic capsules + dynamic routing -> g_vote (K,M,C flat)
// ============================================================================
__global__ __launch_bounds__(256) void capsule_kernel(
    const float* __restrict__ x, const int* __restrict__ tptr,
    const float* __restrict__ sem_w, const float* __restrict__ sem_b,
    const float* __restrict__ route_w, float* __restrict__ vote_out)
{
    extern __shared__ float s_semw[];           // [N*H*C] = 23040 floats
    for (int i = threadIdx.x; i < DN*DH*DC; i += 256) s_semw[i] = sem_w[i];
    __syncthreads();

    const int t = *tptr;
    const int warp = threadIdx.x >> 5;
    const int lane = threadIdx.x & 31;

    for (int tt = 0; tt < 2; tt++) {
        const int m = blockIdx.x*16 + warp*2 + tt;
        const float* xr = x + (size_t)m*DH;

        float acc[30];
        #pragma unroll
        for (int q = 0; q < 30; q++) acc[q] = 0.f;

        #pragma unroll 4
        for (int hb = 0; hb < DH/32; hb++) {
            const int h = hb*32 + lane;
            const float xv = xr[h];
            const float* wp = s_semw + h*3;
            #pragma unroll
            for (int q = 0; q < 30; q++) {
                acc[q] += xv * wp[(q/3)*(DH*DC) + (q%3)];
            }
        }
        #pragma unroll
        for (int q = 0; q < 30; q++) {
            #pragma unroll
            for (int off = 16; off > 0; off >>= 1)
                acc[q] += __shfl_xor_sync(0xffffffffu, acc[q], off);
        }

        if (lane == 0) {
            float semv[30];
            #pragma unroll
            for (int q = 0; q < 30; q++) semv[q] = acc[q] + sem_b[q];

            float fc[3];
            #pragma unroll
            for (int c = 0; c < 3; c++) {
                float sn = 1e-16f;
                #pragma unroll
                for (int n = 0; n < 10; n++) { float v = semv[n*3+c]; sn += v*v; }
                fc[c] = sn/(1.f+sn)*rsqrtf(sn);
            }
            float u[10][3];
            #pragma unroll
            for (int p = 0; p < 30; p++) {
                const int c = p/10, n = p%10;
                u[p/3][p%3] = semv[n*3+c]*fc[c];
            }
            float pri[3][10][3];
            #pragma unroll
            for (int k = 0; k < 3; k++)
                #pragma unroll
                for (int n = 0; n < 10; n++)
                    #pragma unroll
                    for (int d = 0; d < 3; d++) {
                        float s = 0.f;
                        #pragma unroll
                        for (int c = 0; c < 3; c++)
                            s += u[n][c]*route_w[((k*10+n)*3+c)*3+d];
                        pri[k][n][d] = s;
                    }
            float logits[3][10];
            #pragma unroll
            for (int k = 0; k < 3; k++)
                #pragma unroll
                for (int n = 0; n < 10; n++) logits[k][n] = 0.f;
            float vote[3][3];
            #pragma unroll
            for (int it = 0; it < 3; it++) {
                #pragma unroll
                for (int k = 0; k < 3; k++) {
                    float l[10], mx = -1e30f;
                    #pragma unroll
                    for (int n = 0; n < 10; n++) {
                        l[n] = (n <= t) ? logits[k][n] : -10000.f;
                        mx = fmaxf(mx, l[n]);
                    }
                    float e[10], se = 0.f;
                    #pragma unroll
                    for (int n = 0; n < 10; n++) { e[n] = expf(l[n]-mx); se += e[n]; }
                    const float inv = 1.f/se;
                    #pragma unroll
                    for (int d = 0; d < 3; d++) {
                        float v = 0.f;
                        #pragma unroll
                        for (int n = 0; n < 10; n++) v += e[n]*pri[k][n][d];
                        vote[k][d] = v*inv;
                    }
                    if (it < 2) {
                        float sn = 1e-16f;
                        #pragma unroll
                        for (int d = 0; d < 3; d++) sn += vote[k][d]*vote[k][d];
                        const float fo = sn/(1.f+sn)*rsqrtf(sn);
                        #pragma unroll
                        for (int n = 0; n < 10; n++) {
                            float dv = 0.f;
                            #pragma unroll
                            for (int d = 0; d < 3; d++) dv += pri[k][n][d]*vote[k][d];
                            logits[k][n] += dv*fo;
                        }
                    }
                }
            }
            #pragma unroll
            for (int k = 0; k < 3; k++)
                #pragma unroll
                for (int d = 0; d < 3; d++)
                    vote_out[((size_t)k*MTOK + m)*3 + d] = vote[k][d];
        }
    }
}

// ============================================================================
// Kernel 2: h2 = x + (v9 @ larger_w + larger_b) * sigmoid(s*elarger[t])
// ============================================================================
__global__ __launch_bounds__(256) void larger_kernel(
    const float* __restrict__ x, const int* __restrict__ tptr,
    const int* __restrict__ sptr,
    const float* __restrict__ lw, const float* __restrict__ lb,
    const float* __restrict__ elarger, const float* __restrict__ voteflat,
    float* __restrict__ h2)
{
    __shared__ float s_lw[9*DH];
    __shared__ float s_lb[DH];
    __shared__ float s_g[DH];
    __shared__ float s_v[32*9];

    const int t = *tptr;
    const float sf = (float)(*sptr);

    for (int i = threadIdx.x; i < 9*DH; i += 256) s_lw[i] = lw[i];
    for (int i = threadIdx.x; i < DH; i += 256) {
        s_lb[i] = lb[i];
        s_g[i]  = sigmoidf_(sf*elarger[t*DH + i]);
    }
    const int m0 = blockIdx.x*32;
    for (int i = threadIdx.x; i < 32*9; i += 256)
        s_v[i] = voteflat[(size_t)m0*9 + i];
    __syncthreads();

    for (int tt = 0; tt < 32; tt++) {
        const int m = m0 + tt;
        float v[9];
        #pragma unroll
        for (int j = 0; j < 9; j++) v[j] = s_v[tt*9 + j];
        #pragma unroll
        for (int r = 0; r < 3; r++) {
            const int e = threadIdx.x + r*256;
            float a = s_lb[e];
            #pragma unroll
            for (int j = 0; j < 9; j++) a += v[j]*s_lw[j*DH + e];
            h2[(size_t)m*DH + e] = x[(size_t)m*DH + e] + a*s_g[e];
        }
    }
}

// ============================================================================
// Kernels 3/4: tf32 tensor-core GEMM 128x128x32, mma.m16n8k8, cp.async double
// buffering. 8 warps in 2x4 grid, warp tile 64x32, 64 fp32 acc/thread.
// MODE 0: C = gelu(A@B + bias)*gate           (fc1 -> a1)
// MODE 1: C = xres + gelu(A@B + bias)*gate    (fc2 -> out)
// ============================================================================
#define ASTRIDE 36              // 128x32 A tile, [m][k] pad 4 -> banks 4g+r unique
#define BSTRIDE 136             // 32x128 B tile, [k][n] pad 8 -> banks 8r+g unique
#define ASZ (128*ASTRIDE)       // words per stage
#define BSZ (32*BSTRIDE)
#define GEMM_SMEM ((2*ASZ + 2*BSZ)*4)   // 71680 bytes

template<int MODE, int ND, int KD>
__global__ __launch_bounds__(256, 2) void gemm_tc(
    const float* __restrict__ A, const float* __restrict__ Bw,
    const float* __restrict__ bias, const float* __restrict__ egate,
    const int* __restrict__ tptr, const int* __restrict__ sptr,
    const float* __restrict__ xres, float* __restrict__ C)
{
    constexpr int BK = 32;
    constexpr int KT = KD/BK;
    extern __shared__ float smem[];
    float* Abuf = smem;             // 2 stages of ASZ
    float* Bbuf = smem + 2*ASZ;     // 2 stages of BSZ

    const int tid  = threadIdx.x;
    const int warp = tid >> 5, lane = tid & 31;
    const int wm = warp >> 2, wn = warp & 3;       // 2 x 4 warp grid
    const int g = lane >> 2, r = lane & 3;
    const int rowBase = blockIdx.y*128, colBase = blockIdx.x*128;

    const float* Ag = A  + (size_t)rowBase*KD;
    const float* Bg = Bw + colBase;

    float acc[4][4][4];
    #pragma unroll
    for (int i = 0; i < 4; i++)
        #pragma unroll
        for (int j = 0; j < 4; j++)
            #pragma unroll
            for (int e = 0; e < 4; e++) acc[i][j][e] = 0.f;

    // ---- async tile loader ----
    auto loadTiles = [&](int kt, int s) {
        float* As = Abuf + s*ASZ;
        float* Bs = Bbuf + s*BSZ;
        const int k0 = kt*BK;
        #pragma unroll
        for (int i = 0; i < 4; i++) {                 // A: 128 rows x 128B
            const int cid = i*256 + tid;
            const int ar = cid >> 3, ac = (cid & 7)*4;
            uint32_t dst = (uint32_t)__cvta_generic_to_shared(As + ar*ASTRIDE + ac);
            const float* src = Ag + (size_t)ar*KD + k0 + ac;
            asm volatile("cp.async.cg.shared.global [%0], [%1], 16;\n" :: "r"(dst), "l"(src));
        }
        #pragma unroll
        for (int i = 0; i < 4; i++) {                 // B: 32 rows x 512B
            const int cid = i*256 + tid;
            const int br = cid >> 5, bc = (cid & 31)*4;
            uint32_t dst = (uint32_t)__cvta_generic_to_shared(Bs + br*BSTRIDE + bc);
            const float* src = Bg + (size_t)(k0 + br)*ND + bc;
            asm volatile("cp.async.cg.shared.global [%0], [%1], 16;\n" :: "r"(dst), "l"(src));
        }
        asm volatile("cp.async.commit_group;\n");
    };

    loadTiles(0, 0);

    for (int kt = 0; kt < KT; kt++) {
        const int s = kt & 1;
        if (kt + 1 < KT) {
            loadTiles(kt + 1, s ^ 1);
            asm volatile("cp.async.wait_group 1;\n");
        } else {
            asm volatile("cp.async.wait_group 0;\n");
        }
        __syncthreads();

        const float* As = Abuf + s*ASZ;
        const float* Bs = Bbuf + s*BSZ;

        #pragma unroll
        for (int ks = 0; ks < 4; ks++) {              // 4 x k8 steps per tile
            uint32_t a[4][4], b[4][2];
            const float* Abase = As + (wm*64 + g)*ASTRIDE + ks*8 + r;
            #pragma unroll
            for (int mt = 0; mt < 4; mt++) {
                const float* ap = Abase + mt*16*ASTRIDE;
                a[mt][0] = __float_as_uint(ap[0]);
                a[mt][1] = __float_as_uint(ap[8*ASTRIDE]);
                a[mt][2] = __float_as_uint(ap[4]);
                a[mt][3] = __float_as_uint(ap[8*ASTRIDE + 4]);
            }
            const float* Bbase = Bs + (ks*8 + r)*BSTRIDE + wn*32 + g;
            #pragma unroll
            for (int nt = 0; nt < 4; nt++) {
                b[nt][0] = __float_as_uint(Bbase[nt*8]);
                b[nt][1] = __float_as_uint(Bbase[4*BSTRIDE + nt*8]);
            }
            #pragma unroll
            for (int mt = 0; mt < 4; mt++)
                #pragma unroll
                for (int nt = 0; nt < 4; nt++)
                    asm volatile(
                        "mma.sync.aligned.m16n8k8.row.col.f32.tf32.tf32.f32 "
                        "{%0,%1,%2,%3}, {%4,%5,%6,%7}, {%8,%9}, {%0,%1,%2,%3};\n"
                        : "+f"(acc[mt][nt][0]), "+f"(acc[mt][nt][1]),
                          "+f"(acc[mt][nt][2]), "+f"(acc[mt][nt][3])
                        : "r"(a[mt][0]), "r"(a[mt][1]), "r"(a[mt][2]), "r"(a[mt][3]),
                          "r"(b[nt][0]), "r"(b[nt][1]));
        }
        __syncthreads();
    }

    // ---- fused epilogue: bias + exact GELU + HAT gate (+ residual) ----
    const int t = *tptr;
    const float sf = (float)(*sptr);
    const int ncol0 = colBase + wn*32 + 2*r;
    float bb[4][2], gg[4][2];
    #pragma unroll
    for (int nt = 0; nt < 4; nt++)
        #pragma unroll
        for (int e = 0; e < 2; e++) {
            const int n = ncol0 + nt*8 + e;
            bb[nt][e] = bias[n];
            gg[nt][e] = sigmoidf_(sf*egate[t*ND + n]);
        }
    #pragma unroll
    for (int mt = 0; mt < 4; mt++)
        #pragma unroll
        for (int half = 0; half < 2; half++) {
            const size_t row = rowBase + wm*64 + mt*16 + g + half*8;
            const float* xr = (MODE == 1) ? (xres + row*ND) : nullptr;
            float* cr = C + row*ND;
            #pragma unroll
            for (int nt = 0; nt < 4; nt++) {
                const int n = ncol0 + nt*8;
                float v0 = gelu_exact(acc[mt][nt][half*2+0] + bb[nt][0])*gg[nt][0];
                float v1 = gelu_exact(acc[mt][nt][half*2+1] + bb[nt][1])*gg[nt][1];
                if (MODE == 1) {
                    v0 += xr[n];
                    v1 += xr[n + 1];
                }
                *(float2*)(cr + n) = make_float2(v0, v1);
            }
        }
}

// ============================================================================
extern "C" void kernel_launch(void* const* d_in, const int* in_sizes, int n_in,
                              void* d_out, int out_size)
{
    const float* x       = (const float*)d_in[0];
    const int*   tptr    = (const int*)  d_in[1];
    const int*   sptr    = (const int*)  d_in[2];
    const float* fc1_w   = (const float*)d_in[3];
    const float* fc1_b   = (const float*)d_in[4];
    const float* fc2_w   = (const float*)d_in[5];
    const float* fc2_b   = (const float*)d_in[6];
    const float* efc1    = (const float*)d_in[7];
    const float* efc2    = (const float*)d_in[8];
    const float* sem_w   = (const float*)d_in[9];
    const float* sem_b   = (const float*)d_in[10];
    const float* route_w = (const float*)d_in[11];
    const float* lw      = (const float*)d_in[12];
    const float* lb      = (const float*)d_in[13];
    const float* elarger = (const float*)d_in[14];
    float* out = (float*)d_out;

    float *vote, *h2, *a1;
    cudaGetSymbolAddress((void**)&vote, g_vote);
    cudaGetSymbolAddress((void**)&h2,   g_h2);
    cudaGetSymbolAddress((void**)&a1,   g_a1);

    const int capsule_smem = DN*DH*DC*(int)sizeof(float);   // 92160
    cudaFuncSetAttribute(capsule_kernel,
                         cudaFuncAttributeMaxDynamicSharedMemorySize, capsule_smem);
    cudaFuncSetAttribute(gemm_tc<0, DA, DH>,
                         cudaFuncAttributeMaxDynamicSharedMemorySize, GEMM_SMEM);
    cudaFuncSetAttribute(gemm_tc<1, DH, DA>,
                         cudaFuncAttributeMaxDynamicSharedMemorySize, GEMM_SMEM);

    capsule_kernel<<<MTOK/16, 256, capsule_smem>>>(x, tptr, sem_w, sem_b, route_w, vote);
    larger_kernel<<<MTOK/32, 256>>>(x, tptr, sptr, lw, lb, elarger, vote, h2);
    gemm_tc<0, DA, DH><<<dim3(DA/128, MTOK/128), 256, GEMM_SMEM>>>(
        h2, fc1_w, fc1_b, efc1, tptr, sptr, nullptr, a1);
    gemm_tc<1, DH, DA><<<dim3(DH/128, MTOK/128), 256, GEMM_SMEM>>>(
        a1, fc2_w, fc2_b, efc2, tptr, sptr, x, out);
}